// round 4
// baseline (speedup 1.0000x reference)
#include <cuda_runtime.h>
#include <cuda_bf16.h>

#define MODIFIER_COL 11
#define OWNER_COL    24
#define MAXG         8192
#define F_DIM        128

// Persistent scratch (no cudaMalloc allowed). Zero-initialized at load; the
// last block resets everything after consuming it, so each graph replay
// starts clean (deterministic).
__device__ float g_cnt[MAXG];
__device__ float g_s0[MAXG];
__device__ float g_s1[MAXG];
__device__ unsigned int g_done;

// R2's proven reduce body (1 row/thread, warp segreduce over sorted keys,
// ~1 atomic triple per warp-segment) + last-block-done finalize tail.
__global__ __launch_bounds__(256) void fused_kernel(
    const float* __restrict__ nf,
    const int*   __restrict__ batch,
    const float* __restrict__ W1,   // [32,2]
    const float* __restrict__ b1,   // [32]
    const float* __restrict__ W2,   // [1,32]
    const float* __restrict__ b2,   // [1]
    float* __restrict__ out,
    int N, int G)
{
    const int i    = blockIdx.x * blockDim.x + threadIdx.x;
    const int lane = threadIdx.x & 31;

    int   g  = -1;
    float c  = 0.f, v0 = 0.f, v1 = 0.f;
    if (i < N) {
        g  = batch[i];
        const float* row = nf + (size_t)i * F_DIM;
        v0 = __ldg(row + MODIFIER_COL);
        v1 = __ldg(row + OWNER_COL);
        c  = 1.f;
    }

    // Down-sweep segmented reduction (keys non-decreasing across lanes).
    #pragma unroll
    for (int d = 1; d < 32; d <<= 1) {
        int   go = __shfl_down_sync(0xffffffffu, g,  d);
        float co = __shfl_down_sync(0xffffffffu, c,  d);
        float a0 = __shfl_down_sync(0xffffffffu, v0, d);
        float a1 = __shfl_down_sync(0xffffffffu, v1, d);
        if (lane + d < 32 && go == g) { c += co; v0 += a0; v1 += a1; }
    }

    int  gprev = __shfl_up_sync(0xffffffffu, g, 1);
    bool head  = (lane == 0) || (gprev != g);
    if (head && g >= 0 && g < MAXG) {
        atomicAdd(&g_cnt[g], c);
        atomicAdd(&g_s0[g],  v0);
        atomicAdd(&g_s1[g],  v1);
    }

    // ---- last-block-done: finalize MLP + scratch reset, in-kernel ---------
    __threadfence();
    __syncthreads();

    __shared__ bool is_last;
    if (threadIdx.x == 0) {
        unsigned int prev = atomicAdd(&g_done, 1u);
        is_last = (prev == gridDim.x - 1);
    }
    __syncthreads();
    if (!is_last) return;

    for (int gg = threadIdx.x; gg < G; gg += blockDim.x) {
        float cc = g_cnt[gg];
        float t0 = g_s0[gg];
        float t1 = g_s1[gg];
        g_cnt[gg] = 0.f; g_s0[gg] = 0.f; g_s1[gg] = 0.f;  // reset for replay

        float denom = fmaxf(cc, 1.f);
        float f0 = 1.f - t0 / denom;
        float f1 = 1.f - t1 / denom;

        float acc = __ldg(b2);
        #pragma unroll
        for (int j = 0; j < 32; ++j) {
            float h = fmaf(f0, __ldg(W1 + 2 * j),
                      fmaf(f1, __ldg(W1 + 2 * j + 1), __ldg(b1 + j)));
            h   = fmaxf(h, 0.f);
            acc = fmaf(__ldg(W2 + j), h, acc);
        }
        float score = 1.f / (1.f + __expf(-acc));
        out[gg] = (cc > 0.f) ? score : 0.f;
    }
    __threadfence();
    if (threadIdx.x == 0) g_done = 0u;   // reset counter for next replay
}

extern "C" void kernel_launch(void* const* d_in, const int* in_sizes, int n_in,
                              void* d_out, int out_size)
{
    // order: node_features, batch, graph_embedding, W1, b1, W2, b2
    const float* nf    = (const float*)d_in[0];
    const int*   batch = (const int*)d_in[1];
    const float* W1    = (const float*)d_in[3];
    const float* b1    = (const float*)d_in[4];
    const float* W2    = (const float*)d_in[5];
    const float* b2    = (const float*)d_in[6];
    float*       out   = (float*)d_out;

    int N = in_sizes[1];
    int G = in_sizes[2] / F_DIM;
    if (G <= 0 || G > MAXG) G = out_size;

    int blocks = (N + 255) / 256;
    fused_kernel<<<blocks, 256>>>(nf, batch, W1, b1, W2, b2, out, N, G);
}

// round 5
// speedup vs baseline: 1.5598x; 1.5598x over previous
#include <cuda_runtime.h>
#include <cuda_bf16.h>

#define MODIFIER_COL 11
#define OWNER_COL    24
#define MAXG         8192
#define F_DIM        128

// Persistent scratch (no cudaMalloc allowed). Zero-initialized at load;
// finalize_kernel resets the used range after consuming it, so each graph
// replay starts clean (deterministic).
__device__ float g_cnt[MAXG];
__device__ float g_s0[MAXG];
__device__ float g_s1[MAXG];

// ---- R2's proven reduce: 1 row/thread, warp segreduce over sorted keys,
// ~1 atomic triple per warp-segment. Sits at the ~132MB traffic floor. ----
__global__ __launch_bounds__(256) void reduce_kernel(
    const float* __restrict__ nf,
    const int*   __restrict__ batch,
    int N)
{
    const int i    = blockIdx.x * blockDim.x + threadIdx.x;
    const int lane = threadIdx.x & 31;

    int   g  = -1;
    float c  = 0.f, v0 = 0.f, v1 = 0.f;
    if (i < N) {
        g  = batch[i];
        const float* row = nf + (size_t)i * F_DIM;
        v0 = __ldg(row + MODIFIER_COL);
        v1 = __ldg(row + OWNER_COL);
        c  = 1.f;
    }

    // Down-sweep segmented reduction (keys non-decreasing across lanes).
    #pragma unroll
    for (int d = 1; d < 32; d <<= 1) {
        int   go = __shfl_down_sync(0xffffffffu, g,  d);
        float co = __shfl_down_sync(0xffffffffu, c,  d);
        float a0 = __shfl_down_sync(0xffffffffu, v0, d);
        float a1 = __shfl_down_sync(0xffffffffu, v1, d);
        if (lane + d < 32 && go == g) { c += co; v0 += a0; v1 += a1; }
    }

    int  gprev = __shfl_up_sync(0xffffffffu, g, 1);
    bool head  = (lane == 0) || (gprev != g);
    if (head && g >= 0 && g < MAXG) {
        atomicAdd(&g_cnt[g], c);
        atomicAdd(&g_s0[g],  v0);
        atomicAdd(&g_s1[g],  v1);
    }
}

// ---- Finalize: weights staged once per block into SMEM (129 floats), so
// each thread does only 3 global loads (L2-resident: written by atomics).
// 128-thread blocks x 16 -> cold weight fetches spread across 16 SMs. ----
__global__ __launch_bounds__(128) void finalize_kernel(
    const float* __restrict__ W1,   // [32,2] row-major
    const float* __restrict__ b1,   // [32]
    const float* __restrict__ W2,   // [1,32]
    const float* __restrict__ b2,   // [1]
    float* __restrict__ out,
    int G)
{
    __shared__ float sW1[64];
    __shared__ float sb1[32];
    __shared__ float sW2[32];
    __shared__ float sb2;

    const int t = threadIdx.x;
    if (t < 64)        sW1[t]      = W1[t];
    else if (t < 96)   sb1[t - 64] = b1[t - 64];
    else               sW2[t - 96] = W2[t - 96];
    if (t == 0)        sb2 = *b2;
    __syncthreads();

    int g = blockIdx.x * blockDim.x + t;
    if (g >= G) return;

    float cc = g_cnt[g];
    float t0 = g_s0[g];
    float t1 = g_s1[g];
    g_cnt[g] = 0.f; g_s0[g] = 0.f; g_s1[g] = 0.f;   // reset for next replay

    float denom = fmaxf(cc, 1.f);
    float f0 = 1.f - t0 / denom;
    float f1 = 1.f - t1 / denom;

    float acc = sb2;
    #pragma unroll
    for (int j = 0; j < 32; ++j) {
        float h = fmaf(f0, sW1[2 * j], fmaf(f1, sW1[2 * j + 1], sb1[j]));
        h   = fmaxf(h, 0.f);
        acc = fmaf(sW2[j], h, acc);
    }
    float score = 1.f / (1.f + __expf(-acc));
    out[g] = (cc > 0.f) ? score : 0.f;
}

extern "C" void kernel_launch(void* const* d_in, const int* in_sizes, int n_in,
                              void* d_out, int out_size)
{
    // order: node_features, batch, graph_embedding, W1, b1, W2, b2
    const float* nf    = (const float*)d_in[0];
    const int*   batch = (const int*)d_in[1];
    const float* W1    = (const float*)d_in[3];
    const float* b1    = (const float*)d_in[4];
    const float* W2    = (const float*)d_in[5];
    const float* b2    = (const float*)d_in[6];
    float*       out   = (float*)d_out;

    int N = in_sizes[1];
    int G = in_sizes[2] / F_DIM;
    if (G <= 0 || G > MAXG) G = out_size;

    int rb = (N + 255) / 256;
    reduce_kernel<<<rb, 256>>>(nf, batch, N);

    int fb = (G + 127) / 128;
    finalize_kernel<<<fb, 128>>>(W1, b1, W2, b2, out, G);
}